// round 4
// baseline (speedup 1.0000x reference)
#include <cuda_runtime.h>

// Problem constants (match reference_code)
constexpr int BATCH = 2048;
constexpr int NF    = 512;   // NUM_FOLDS
constexpr int FD    = 64;    // FOLD_DIM
constexpr int NL    = 4;     // NUM_LAYERS
constexpr int NOUT  = 8;     // NUM_OUTPUTS
constexpr int BM    = 64;    // batch tile per block
constexpr int HS_STRIDE = 68; // 272B row stride: 16B-aligned rows, 2-way write conflict

// Ping-pong activation buffers: 2 x 2048*512*64 fp32 = 2 x 256 MB (static, allowed)
__device__ __align__(256) float g_x0[BATCH * NF * FD];
__device__ __align__(256) float g_x1[BATCH * NF * FD];

// One layer: for fold f, h[b,k] = x[b,i0,k]*x[b,i1,k]; y[b,f,:] = h[b,:] @ W[f]
// Block: (fold, batch-tile of BM rows). 256 threads, each computes a 4x4 output tile.
__global__ __launch_bounds__(256, 4)
void layer_kernel(const float* __restrict__ xin,
                  const float* __restrict__ W,      // [NF][64][64] for this layer
                  const int*   __restrict__ fidx,   // [NF][2] for this layer
                  float*       __restrict__ xout)
{
    const int f   = blockIdx.x;
    const int m0  = blockIdx.y * BM;
    const int tid = threadIdx.x;

    __shared__ float ws[64][64];              // ws[k][n] = W[f][k][n]
    __shared__ float hs[64][HS_STRIDE];       // hs[k][m] (transposed h tile)

    const int i0 = fidx[2 * f];
    const int i1 = fidx[2 * f + 1];

    // Load W[f] (4096 floats) via float4
    const float4* Wf4 = reinterpret_cast<const float4*>(W + (size_t)f * 64 * 64);
    float4* ws4 = reinterpret_cast<float4*>(&ws[0][0]);
    #pragma unroll
    for (int i = tid; i < 1024; i += 256)
        ws4[i] = Wf4[i];

    // Fused gather + product, store transposed into hs
    const float* xr0 = xin + i0 * FD;
    const float* xr1 = xin + i1 * FD;
    #pragma unroll
    for (int i = tid; i < BM * (FD / 4); i += 256) {
        const int m  = i >> 4;         // 0..63
        const int kq = i & 15;         // float4 index along k
        const int boff = (m0 + m) * (NF * FD);
        const float4 a = *reinterpret_cast<const float4*>(xr0 + boff + kq * 4);
        const float4 b = *reinterpret_cast<const float4*>(xr1 + boff + kq * 4);
        hs[kq * 4 + 0][m] = a.x * b.x;
        hs[kq * 4 + 1][m] = a.y * b.y;
        hs[kq * 4 + 2][m] = a.z * b.z;
        hs[kq * 4 + 3][m] = a.w * b.w;
    }
    __syncthreads();

    // Register-blocked GEMM: thread (tm, tn) computes out rows [tm*4, tm*4+4),
    // cols [tn*4, tn*4+4)
    const int tm = tid >> 4;   // 0..15
    const int tn = tid & 15;   // 0..15

    float acc[4][4];
    #pragma unroll
    for (int i = 0; i < 4; i++)
        #pragma unroll
        for (int j = 0; j < 4; j++)
            acc[i][j] = 0.0f;

    #pragma unroll 8
    for (int k = 0; k < 64; k++) {
        // hs row start is 272B-aligned (multiple of 16B); tm*4 floats offset keeps 16B align.
        const float4 a = *reinterpret_cast<const float4*>(&hs[k][tm * 4]);
        const float4 b = *reinterpret_cast<const float4*>(&ws[k][tn * 4]);
        acc[0][0] += a.x * b.x; acc[0][1] += a.x * b.y; acc[0][2] += a.x * b.z; acc[0][3] += a.x * b.w;
        acc[1][0] += a.y * b.x; acc[1][1] += a.y * b.y; acc[1][2] += a.y * b.z; acc[1][3] += a.y * b.w;
        acc[2][0] += a.z * b.x; acc[2][1] += a.z * b.y; acc[2][2] += a.z * b.z; acc[2][3] += a.z * b.w;
        acc[3][0] += a.w * b.x; acc[3][1] += a.w * b.y; acc[3][2] += a.w * b.z; acc[3][3] += a.w * b.w;
    }

    // Write back: xout[(m0 + tm*4 + i) * NF*FD + f*FD + tn*4 .. +3]
    #pragma unroll
    for (int i = 0; i < 4; i++) {
        float4 v = make_float4(acc[i][0], acc[i][1], acc[i][2], acc[i][3]);
        *reinterpret_cast<float4*>(xout + (size_t)(m0 + tm * 4 + i) * (NF * FD)
                                        + f * FD + tn * 4) = v;
    }
}

// Final gather: out[b, o, :] = x[b, out_idx[o], :]
__global__ void gather_kernel(const float* __restrict__ x,
                              const int* __restrict__ oidx,
                              float* __restrict__ out)
{
    const int t = blockIdx.x * blockDim.x + threadIdx.x;  // one float4 each
    const int total = BATCH * NOUT * (FD / 4);
    if (t >= total) return;
    const int q = t & 15;                 // float4 index in fold dim
    const int o = (t >> 4) & (NOUT - 1);
    const int b = t >> 7;                 // /(16*8)
    const int src = b * (NF * FD) + oidx[o] * FD + q * 4;
    reinterpret_cast<float4*>(out)[t] =
        *reinterpret_cast<const float4*>(x + src);
}

extern "C" void kernel_launch(void* const* d_in, const int* in_sizes, int n_in,
                              void* d_out, int out_size)
{
    const float* in_graph = (const float*)d_in[0];   // [2048, 512, 64] f32
    const float* weights  = (const float*)d_in[1];   // [4, 512, 64, 64] f32
    const int*   fold_idx = (const int*)d_in[2];     // [4, 512, 2] i32
    const int*   out_idx  = (const int*)d_in[3];     // [8] i32
    float*       out      = (float*)d_out;           // [2048, 8, 64] f32

    float *p0 = nullptr, *p1 = nullptr;
    cudaGetSymbolAddress((void**)&p0, g_x0);
    cudaGetSymbolAddress((void**)&p1, g_x1);

    const size_t w_stride = (size_t)NF * FD * FD;    // floats per layer
    const size_t i_stride = (size_t)NF * 2;          // ints per layer

    dim3 grid(NF, BATCH / BM);
    dim3 block(256);

    // Layer 0: in_graph -> p0
    layer_kernel<<<grid, block>>>(in_graph, weights + 0 * w_stride,
                                  fold_idx + 0 * i_stride, p0);
    // Layer 1: p0 -> p1
    layer_kernel<<<grid, block>>>(p0, weights + 1 * w_stride,
                                  fold_idx + 1 * i_stride, p1);
    // Layer 2: p1 -> p0
    layer_kernel<<<grid, block>>>(p1, weights + 2 * w_stride,
                                  fold_idx + 2 * i_stride, p0);
    // Layer 3: p0 -> p1
    layer_kernel<<<grid, block>>>(p0, weights + 3 * w_stride,
                                  fold_idx + 3 * i_stride, p1);

    // Output gather from final buffer
    const int total = BATCH * NOUT * (FD / 4);
    gather_kernel<<<(total + 255) / 256, 256>>>(p1, out_idx, out);
}

// round 5
// speedup vs baseline: 1.2023x; 1.2023x over previous
#include <cuda_runtime.h>

// Problem constants (match reference_code)
constexpr int BATCH = 2048;
constexpr int NF    = 512;   // NUM_FOLDS
constexpr int FD    = 64;    // FOLD_DIM
constexpr int NOUT  = 8;     // NUM_OUTPUTS
constexpr int BM    = 256;   // batch tile per block
constexpr int SMEM_BYTES = (64 * 64 + 64 * BM) * 4;  // ws 16KB + hs 64KB = 80KB

// Ping-pong activation buffers: 2 x 2048*512*64 fp32 = 2 x 256 MB (static, allowed)
__device__ __align__(256) float g_x0[BATCH * NF * FD];
__device__ __align__(256) float g_x1[BATCH * NF * FD];

// One layer: for fold f, h[b,k] = x[b,i0,k]*x[b,i1,k]; y[b,f,:] = h[b,:] @ W[f]
// Block: (fold f, 256-row batch tile). 256 threads, 8x8 register tiles (rows split
// 4+4 at +128, cols split 4+4 at +32).
//
// hs layout: [k][m] 64x256 floats, with a 16B-word XOR swizzle:
//   word w = m>>2, physical word pw = w ^ ((k>>2)&7), scalar at pw*4 + (m&3).
// This makes the transpose-store 2-way (vs 8-way naive) and keeps vectorized
// a-reads conflict-free.
__global__ __launch_bounds__(256, 2)
void layer_kernel(const float* __restrict__ xin,
                  const float* __restrict__ W,      // [NF][64][64] for this layer
                  const int*   __restrict__ fidx,   // [NF][2] for this layer
                  float*       __restrict__ xout)
{
    extern __shared__ float smem[];
    float* ws = smem;            // [64][64]  ws[k*64 + n] = W[f][k][n]
    float* hs = smem + 64 * 64;  // [64][256] swizzled, see above

    const int f   = blockIdx.x;
    const int m0  = blockIdx.y * BM;
    const int tid = threadIdx.x;

    const int i0 = fidx[2 * f];
    const int i1 = fidx[2 * f + 1];

    // Load W[f] (4096 floats) via float4
    const float4* Wf4 = reinterpret_cast<const float4*>(W + (size_t)f * 64 * 64);
    float4* ws4 = reinterpret_cast<float4*>(ws);
    #pragma unroll
    for (int i = tid; i < 1024; i += 256)
        ws4[i] = Wf4[i];

    // Fused gather + product, store transposed+swizzled into hs.
    // item i -> (m = i>>4, kq = i&15); writes k = 4*kq + j, j=0..3.
    const float* xr0 = xin + (size_t)i0 * FD;
    const float* xr1 = xin + (size_t)i1 * FD;
    #pragma unroll
    for (int it = 0; it < 16; it++) {
        const int i  = it * 256 + tid;
        const int m  = i >> 4;         // 0..255
        const int kq = i & 15;         // float4 index along k
        const size_t boff = (size_t)(m0 + m) * (NF * FD);
        const float4 a = *reinterpret_cast<const float4*>(xr0 + boff + kq * 4);
        const float4 b = *reinterpret_cast<const float4*>(xr1 + boff + kq * 4);
        const int pw = (m >> 2) ^ (kq & 7);          // (k>>2)&7 == kq&7 for all j
        float* dst = &hs[kq * 4 * BM + pw * 4 + (m & 3)];
        dst[0 * BM] = a.x * b.x;
        dst[1 * BM] = a.y * b.y;
        dst[2 * BM] = a.z * b.z;
        dst[3 * BM] = a.w * b.w;
    }
    __syncthreads();

    // 8x8 register-tile GEMM.
    // tm = tid>>3 (0..31): rows tm*4..tm*4+3 and +128. tn = tid&7: cols tn*4..+3 and +32.
    const int tm = tid >> 3;
    const int tn = tid & 7;

    float acc[8][8];
    #pragma unroll
    for (int i = 0; i < 8; i++)
        #pragma unroll
        for (int j = 0; j < 8; j++)
            acc[i][j] = 0.0f;

    #pragma unroll 8
    for (int k = 0; k < 64; k++) {
        const int kw = (k >> 2) & 7;
        const int pa = k * BM + ((tm ^ kw) << 2);    // swizzled word for w=tm
        const float4 a0 = *reinterpret_cast<const float4*>(&hs[pa]);         // rows tm*4..+3
        const float4 a1 = *reinterpret_cast<const float4*>(&hs[pa + 128]);   // rows +128
        const float4 b0 = *reinterpret_cast<const float4*>(&ws[k * 64 + tn * 4]);
        const float4 b1 = *reinterpret_cast<const float4*>(&ws[k * 64 + tn * 4 + 32]);

        const float av[8] = {a0.x, a0.y, a0.z, a0.w, a1.x, a1.y, a1.z, a1.w};
        const float bv[8] = {b0.x, b0.y, b0.z, b0.w, b1.x, b1.y, b1.z, b1.w};
        #pragma unroll
        for (int i = 0; i < 8; i++)
            #pragma unroll
            for (int j = 0; j < 8; j++)
                acc[i][j] += av[i] * bv[j];
    }

    // Write back. Row groups: m0 + tm*4 + i (acc rows 0..3) and +128 (acc rows 4..7).
    // Col groups: f*64 + tn*4 (acc cols 0..3) and +32 (acc cols 4..7).
    #pragma unroll
    for (int i = 0; i < 4; i++) {
        const size_t r0 = (size_t)(m0 + tm * 4 + i) * (NF * FD) + f * FD;
        const size_t r1 = (size_t)(m0 + 128 + tm * 4 + i) * (NF * FD) + f * FD;
        *reinterpret_cast<float4*>(xout + r0 + tn * 4) =
            make_float4(acc[i][0], acc[i][1], acc[i][2], acc[i][3]);
        *reinterpret_cast<float4*>(xout + r0 + tn * 4 + 32) =
            make_float4(acc[i][4], acc[i][5], acc[i][6], acc[i][7]);
        *reinterpret_cast<float4*>(xout + r1 + tn * 4) =
            make_float4(acc[i + 4][0], acc[i + 4][1], acc[i + 4][2], acc[i + 4][3]);
        *reinterpret_cast<float4*>(xout + r1 + tn * 4 + 32) =
            make_float4(acc[i + 4][4], acc[i + 4][5], acc[i + 4][6], acc[i + 4][7]);
    }
}

// Final gather: out[b, o, :] = x[b, out_idx[o], :]
__global__ void gather_kernel(const float* __restrict__ x,
                              const int* __restrict__ oidx,
                              float* __restrict__ out)
{
    const int t = blockIdx.x * blockDim.x + threadIdx.x;  // one float4 each
    const int total = BATCH * NOUT * (FD / 4);
    if (t >= total) return;
    const int q = t & 15;                 // float4 index in fold dim
    const int o = (t >> 4) & (NOUT - 1);
    const int b = t >> 7;                 // /(16*8)
    const size_t src = (size_t)b * (NF * FD) + (size_t)oidx[o] * FD + q * 4;
    reinterpret_cast<float4*>(out)[t] =
        *reinterpret_cast<const float4*>(x + src);
}

extern "C" void kernel_launch(void* const* d_in, const int* in_sizes, int n_in,
                              void* d_out, int out_size)
{
    const float* in_graph = (const float*)d_in[0];   // [2048, 512, 64] f32
    const float* weights  = (const float*)d_in[1];   // [4, 512, 64, 64] f32
    const int*   fold_idx = (const int*)d_in[2];     // [4, 512, 2] i32
    const int*   out_idx  = (const int*)d_in[3];     // [8] i32
    float*       out      = (float*)d_out;           // [2048, 8, 64] f32

    float *p0 = nullptr, *p1 = nullptr;
    cudaGetSymbolAddress((void**)&p0, g_x0);
    cudaGetSymbolAddress((void**)&p1, g_x1);

    // 80KB dynamic smem needs an opt-in (idempotent, host-side, capture-safe).
    cudaFuncSetAttribute(layer_kernel,
                         cudaFuncAttributeMaxDynamicSharedMemorySize, SMEM_BYTES);

    const size_t w_stride = (size_t)NF * FD * FD;    // floats per layer
    const size_t i_stride = (size_t)NF * 2;          // ints per layer

    dim3 grid(NF, BATCH / BM);
    dim3 block(256);

    layer_kernel<<<grid, block, SMEM_BYTES>>>(in_graph, weights + 0 * w_stride,
                                              fold_idx + 0 * i_stride, p0);
    layer_kernel<<<grid, block, SMEM_BYTES>>>(p0, weights + 1 * w_stride,
                                              fold_idx + 1 * i_stride, p1);
    layer_kernel<<<grid, block, SMEM_BYTES>>>(p1, weights + 2 * w_stride,
                                              fold_idx + 2 * i_stride, p0);
    layer_kernel<<<grid, block, SMEM_BYTES>>>(p0, weights + 3 * w_stride,
                                              fold_idx + 3 * i_stride, p1);

    const int total = BATCH * NOUT * (FD / 4);
    gather_kernel<<<(total + 255) / 256, 256>>>(p1, out_idx, out);
}

// round 7
// speedup vs baseline: 1.8618x; 1.5485x over previous
#include <cuda_runtime.h>
#include <cuda_bf16.h>
#include <cstdint>

// Problem constants
constexpr int BATCH = 2048;
constexpr int NF    = 512;
constexpr int FD    = 64;
constexpr int NOUT  = 8;
constexpr int BM    = 128;   // M-tile per block

// fp32 activation ping-pong (2 x 256 MB)
__device__ __align__(256) float g_x0[BATCH * NF * FD];
__device__ __align__(256) float g_x1[BATCH * NF * FD];
// Pre-split transposed weights: Wt[n][k] = W[k][n], bf16 hi/lo planes.
// Per fold: 64 rows(n) x 64 k packed as 512 uint4 (8 bf16 each).
__device__ __align__(256) uint4 g_wh[4 * 512 * 512];
__device__ __align__(256) uint4 g_wl[4 * 512 * 512];

// SW128 swizzle (Swizzle<3,4,3>) on byte offsets with 128B rows
#define SW(o) ((o) ^ ((((unsigned)(o)) >> 3) & 0x70))

__device__ __forceinline__ uint32_t smem_u32(const void* p) {
    uint32_t a;
    asm("{ .reg .u64 t; cvta.to.shared.u64 t, %1; cvt.u32.u64 %0, t; }" : "=r"(a) : "l"(p));
    return a;
}
__device__ __forceinline__ uint32_t pack_hi_lo(float a, float b, uint32_t& lo) {
    __nv_bfloat162 h2 = __floats2bfloat162_rn(a, b);
    float ra = a - __bfloat162float(h2.x);
    float rb = b - __bfloat162float(h2.y);
    __nv_bfloat162 l2 = __floats2bfloat162_rn(ra, rb);
    lo = *reinterpret_cast<uint32_t*>(&l2);
    return *reinterpret_cast<uint32_t*>(&h2);
}
__device__ __forceinline__ void ldsm_x4(uint32_t* r, uint32_t addr) {
    asm volatile("ldmatrix.sync.aligned.m8n8.x4.shared.b16 {%0,%1,%2,%3}, [%4];"
                 : "=r"(r[0]), "=r"(r[1]), "=r"(r[2]), "=r"(r[3]) : "r"(addr));
}
__device__ __forceinline__ void mma_bf16(float* c, const uint32_t* a,
                                         uint32_t b0, uint32_t b1) {
    asm volatile(
        "mma.sync.aligned.m16n8k16.row.col.f32.bf16.bf16.f32 "
        "{%0,%1,%2,%3}, {%4,%5,%6,%7}, {%8,%9}, {%0,%1,%2,%3};"
        : "+f"(c[0]), "+f"(c[1]), "+f"(c[2]), "+f"(c[3])
        : "r"(a[0]), "r"(a[1]), "r"(a[2]), "r"(a[3]), "r"(b0), "r"(b1));
}

// ---------------- weight prep: transpose + bf16 hi/lo split ----------------
__global__ void wprep_kernel(const float* __restrict__ W) {
    __shared__ float s[64][65];
    const int lf = blockIdx.x;                 // layer*512 + fold
    const float4* Wf4 = reinterpret_cast<const float4*>(W + (size_t)lf * 4096);
    for (int i = threadIdx.x; i < 1024; i += 256) {
        const int k = i >> 4, nq = i & 15;
        float4 v = Wf4[i];
        s[k][nq * 4 + 0] = v.x; s[k][nq * 4 + 1] = v.y;
        s[k][nq * 4 + 2] = v.z; s[k][nq * 4 + 3] = v.w;
    }
    __syncthreads();
    for (int i = threadIdx.x; i < 512; i += 256) {
        const int n = i >> 3, kq = i & 7;      // out row n, 8-k chunk kq
        uint32_t hw[4], lw[4];
        #pragma unroll
        for (int j = 0; j < 4; j++) {
            const float a = s[kq * 8 + j * 2 + 0][n];
            const float b = s[kq * 8 + j * 2 + 1][n];
            hw[j] = pack_hi_lo(a, b, lw[j]);
        }
        g_wh[(size_t)lf * 512 + i] = make_uint4(hw[0], hw[1], hw[2], hw[3]);
        g_wl[(size_t)lf * 512 + i] = make_uint4(lw[0], lw[1], lw[2], lw[3]);
    }
}

// ---------------- HMMA layer kernel ----------------
// Dynamic smem map (bytes): HH 0 (16K), HL 16384 (16K), WH 32768 (8K), WL 40960 (8K).
constexpr int SM_HH = 0, SM_HL = 16384, SM_WH = 32768, SM_WL = 40960;
constexpr int SMEM_BYTES = 49152;

__global__ __launch_bounds__(256, 2)
void layer_mma_kernel(const float* __restrict__ xin,
                      const uint4* __restrict__ wh,   // this layer: [512 folds][512] uint4
                      const uint4* __restrict__ wl,
                      const int*   __restrict__ fidx,
                      float*       __restrict__ xout)
{
    extern __shared__ char smem[];
    const uint32_t sb = smem_u32(smem);
    const int tid = threadIdx.x, wid = tid >> 5, lid = tid & 31;
    const int f = blockIdx.x, m0 = blockIdx.y * BM;

    // --- W tiles (pre-transposed bf16 hi/lo): copy with SW128 swizzle ---
    const uint4* whf = wh + (size_t)f * 512;
    const uint4* wlf = wl + (size_t)f * 512;
    #pragma unroll
    for (int it = 0; it < 2; it++) {
        const int i = it * 256 + tid;          // 0..511
        const int n = i >> 3, q = i & 7;
        const uint32_t off = SW(n * 128 + q * 16);
        *reinterpret_cast<uint4*>(smem + SM_WH + off) = whf[i];
        *reinterpret_cast<uint4*>(smem + SM_WL + off) = wlf[i];
    }

    // --- H tiles: gather + product (fp32), split to bf16 hi/lo, swizzled store ---
    const float* x0 = xin + (size_t)fidx[2 * f + 0] * FD;
    const float* x1 = xin + (size_t)fidx[2 * f + 1] * FD;
    #pragma unroll
    for (int it = 0; it < 4; it++) {
        const int i = it * 256 + tid;          // 0..1023
        const int m = i >> 3, q = i & 7;       // row m (0..127), 8-k chunk q
        const size_t boff = (size_t)(m0 + m) * (NF * FD) + q * 8;
        const float4 a0 = *reinterpret_cast<const float4*>(x0 + boff);
        const float4 a1 = *reinterpret_cast<const float4*>(x0 + boff + 4);
        const float4 b0 = *reinterpret_cast<const float4*>(x1 + boff);
        const float4 b1 = *reinterpret_cast<const float4*>(x1 + boff + 4);
        const float p[8] = { a0.x * b0.x, a0.y * b0.y, a0.z * b0.z, a0.w * b0.w,
                             a1.x * b1.x, a1.y * b1.y, a1.z * b1.z, a1.w * b1.w };
        uint32_t hw[4], lw[4];
        #pragma unroll
        for (int j = 0; j < 4; j++)
            hw[j] = pack_hi_lo(p[2 * j], p[2 * j + 1], lw[j]);
        const uint32_t off = SW(m * 128 + q * 16);
        *reinterpret_cast<uint4*>(smem + SM_HH + off) = make_uint4(hw[0], hw[1], hw[2], hw[3]);
        *reinterpret_cast<uint4*>(smem + SM_HL + off) = make_uint4(lw[0], lw[1], lw[2], lw[3]);
    }
    __syncthreads();

    // --- warp-tiled MMA: 8 warps, warp tile 32(M) x 32(N) ---
    const int wm = wid >> 1;                   // 0..3 -> m offset wm*32
    const int wn = wid & 1;                    //  0..1 -> n offset wn*32
    const int l7 = lid & 7, l8 = (lid >> 3) & 1, l16 = lid >> 4;

    float acc[2][4][4];                        // [mt][nt][frag]
    #pragma unroll
    for (int mt = 0; mt < 2; mt++)
        #pragma unroll
        for (int nt = 0; nt < 4; nt++)
            #pragma unroll
            for (int j = 0; j < 4; j++)
                acc[mt][nt][j] = 0.0f;

    #pragma unroll
    for (int ks = 0; ks < 4; ks++) {
        const int kc = ks * 16 + l16 * 8;      // k column for this lane's ldmatrix
        uint32_t AH[2][4], AL[2][4], BH[2][4], BL[2][4];
        #pragma unroll
        for (int mt = 0; mt < 2; mt++) {
            const int row = wm * 32 + mt * 16 + l7 + l8 * 8;
            const uint32_t off = SW(row * 128 + kc * 2);
            ldsm_x4(AH[mt], sb + SM_HH + off);
            ldsm_x4(AL[mt], sb + SM_HL + off);
        }
        #pragma unroll
        for (int h = 0; h < 2; h++) {
            const int n = wn * 32 + h * 16 + l7 + l8 * 8;
            const uint32_t off = SW(n * 128 + kc * 2);
            ldsm_x4(BH[h], sb + SM_WH + off);
            ldsm_x4(BL[h], sb + SM_WL + off);
        }
        #pragma unroll
        for (int mt = 0; mt < 2; mt++)
            #pragma unroll
            for (int nt = 0; nt < 4; nt++) {
                const int h = nt >> 1, s = nt & 1;
                mma_bf16(acc[mt][nt], AH[mt], BH[h][s], BH[h][s + 2]);
                mma_bf16(acc[mt][nt], AH[mt], BL[h][s], BL[h][s + 2]);
                mma_bf16(acc[mt][nt], AL[mt], BH[h][s], BH[h][s + 2]);
            }
    }

    // --- epilogue: fragment -> GMEM (float2 stores, 128B per row per warp) ---
    const int quad = lid >> 2, qlane = lid & 3;
    #pragma unroll
    for (int mt = 0; mt < 2; mt++) {
        const int r = m0 + wm * 32 + mt * 16 + quad;
        #pragma unroll
        for (int nt = 0; nt < 4; nt++) {
            const int col = f * FD + wn * 32 + nt * 8 + qlane * 2;
            float* d0 = xout + (size_t)r * (NF * FD) + col;
            float* d1 = d0 + (size_t)8 * (NF * FD);
            *reinterpret_cast<float2*>(d0) = make_float2(acc[mt][nt][0], acc[mt][nt][1]);
            *reinterpret_cast<float2*>(d1) = make_float2(acc[mt][nt][2], acc[mt][nt][3]);
        }
    }
}

// Final gather: out[b, o, :] = x[b, out_idx[o], :]
__global__ void gather_kernel(const float* __restrict__ x,
                              const int* __restrict__ oidx,
                              float* __restrict__ out)
{
    const int t = blockIdx.x * blockDim.x + threadIdx.x;
    const int total = BATCH * NOUT * (FD / 4);
    if (t >= total) return;
    const int q = t & 15;
    const int o = (t >> 4) & (NOUT - 1);
    const int b = t >> 7;
    const size_t src = (size_t)b * (NF * FD) + (size_t)oidx[o] * FD + q * 4;
    reinterpret_cast<float4*>(out)[t] = *reinterpret_cast<const float4*>(x + src);
}

extern "C" void kernel_launch(void* const* d_in, const int* in_sizes, int n_in,
                              void* d_out, int out_size)
{
    const float* in_graph = (const float*)d_in[0];
    const float* weights  = (const float*)d_in[1];
    const int*   fold_idx = (const int*)d_in[2];
    const int*   out_idx  = (const int*)d_in[3];
    float*       out      = (float*)d_out;

    float *p0 = nullptr, *p1 = nullptr;
    uint4 *wh = nullptr, *wl = nullptr;
    cudaGetSymbolAddress((void**)&p0, g_x0);
    cudaGetSymbolAddress((void**)&p1, g_x1);
    cudaGetSymbolAddress((void**)&wh, g_wh);
    cudaGetSymbolAddress((void**)&wl, g_wl);

    cudaFuncSetAttribute(layer_mma_kernel,
                         cudaFuncAttributeMaxDynamicSharedMemorySize, SMEM_BYTES);

    // Pre-split + transpose all layer weights into bf16 hi/lo
    wprep_kernel<<<4 * 512, 256>>>(weights);

    const size_t wlayer = (size_t)512 * 512;   // uint4 per layer
    const size_t i_stride = (size_t)NF * 2;

    dim3 grid(NF, BATCH / BM);
    dim3 block(256);

    layer_mma_kernel<<<grid, block, SMEM_BYTES>>>(in_graph, wh + 0 * wlayer, wl + 0 * wlayer,
                                                  fold_idx + 0 * i_stride, p0);
    layer_mma_kernel<<<grid, block, SMEM_BYTES>>>(p0, wh + 1 * wlayer, wl + 1 * wlayer,
                                                  fold_idx + 1 * i_stride, p1);
    layer_mma_kernel<<<grid, block, SMEM_BYTES>>>(p1, wh + 2 * wlayer, wl + 2 * wlayer,
                                                  fold_idx + 2 * i_stride, p0);
    layer_mma_kernel<<<grid, block, SMEM_BYTES>>>(p0, wh + 3 * wlayer, wl + 3 * wlayer,
                                                  fold_idx + 3 * i_stride, p1);

    const int total = BATCH * NOUT * (FD / 4);
    gather_kernel<<<(total + 255) / 256, 256>>>(p1, out_idx, out);
}